// round 2
// baseline (speedup 1.0000x reference)
#include <cuda_runtime.h>
#include <cuda_bf16.h>
#include <math.h>

// ---------------- problem constants ----------------
// B=1, N=6, X=Y=25 (L=625), W1=W2=8 (Qn=384), w1=w2=4 (Kn=96), D=128, M=4 heads, dh=32

#define LTOT 625
#define QN   384
#define KN   96

// ---------------- device scratch (no allocs allowed) ----------------
__device__ __nv_bfloat16 g_qp[(size_t)LTOT * 4 * QN * 32];   // (l, m, t, dh)
__device__ __nv_bfloat16 g_kp[(size_t)LTOT * 4 * KN * 32];
__device__ __nv_bfloat16 g_vp[(size_t)LTOT * 4 * KN * 32];
__device__ __nv_bfloat16 g_att[(size_t)LTOT * QN * 128];     // (l, t, m*32+j)
__device__ __nv_bfloat16 g_wq[16384];
__device__ __nv_bfloat16 g_wkw[16384];
__device__ __nv_bfloat16 g_wv[16384];
__device__ __nv_bfloat16 g_wp[16384];
__device__ float g_cos[QN * 32];
__device__ float g_sin[QN * 32];
__device__ float g_scales[4];

// ---------------- helpers ----------------
__device__ __forceinline__ unsigned pk(float a, float b) {
    __nv_bfloat162 h = __floats2bfloat162_rn(a, b);
    return *reinterpret_cast<unsigned*>(&h);
}

// mma.sync m16n8k16 row.col f32.bf16.bf16.f32
__device__ __forceinline__ void mma16816(float c[4], const unsigned a[4], const unsigned b[2]) {
    asm volatile(
        "mma.sync.aligned.m16n8k16.row.col.f32.bf16.bf16.f32 "
        "{%0,%1,%2,%3}, {%4,%5,%6,%7}, {%8,%9}, {%0,%1,%2,%3};\n"
        : "+f"(c[0]), "+f"(c[1]), "+f"(c[2]), "+f"(c[3])
        : "r"(a[0]), "r"(a[1]), "r"(a[2]), "r"(a[3]), "r"(b[0]), "r"(b[1]));
}

// ---------------- kernel 0: constants prep ----------------
__global__ __launch_bounds__(256) void prep_const_kernel(
    const float* __restrict__ wq, const float* __restrict__ wk,
    const float* __restrict__ wv, const float* __restrict__ wp,
    const float* __restrict__ freqs, const float* __restrict__ gate,
    const float* __restrict__ als)
{
    int idx = blockIdx.x * 256 + threadIdx.x;
    if (idx < 16384) {
        g_wq[idx] = __float2bfloat16(wq[idx]);
    } else if (idx < 32768) {
        g_wkw[idx - 16384] = __float2bfloat16(wk[idx - 16384]);
    } else if (idx < 49152) {
        g_wv[idx - 32768] = __float2bfloat16(wv[idx - 32768]);
    } else if (idx < 65536) {
        g_wp[idx - 49152] = __float2bfloat16(wp[idx - 49152]);
    } else if (idx < 65536 + QN * 32) {
        int j = idx - 65536;
        float f = freqs[j];            // freqs is (400,32) row-major, t<384 prefix
        g_cos[j] = cosf(f);
        g_sin[j] = sinf(f);
    } else if (idx < 65536 + QN * 32 + 4) {
        int m = idx - (65536 + QN * 32);
        float temp = als[m] - 0.5f * logf(32.0f);   // als + log(dh^-0.5)
        float ga = fminf(fmaxf(gate[m], 0.0f), 1.0f);
        g_scales[m] = temp * ga;
    }
}

// ---------------- kernel 1: gather + LayerNorm + Linear + RoPE ----------------
// One block = 32 rows (rows never cross an l boundary since T%32==0).
// sel: 0=q(->g_qp), 1=k(->g_kp), 2=v(->g_vp)
__global__ __launch_bounds__(256) void prep_qkv_kernel(
    const float* __restrict__ x, const float* __restrict__ lng,
    const float* __restrict__ lnb, const float* __restrict__ bias,
    int T, int chunk, int use_rope, int use_scale, int sel)
{
    const __nv_bfloat16* wbf = (sel == 0) ? g_wq : (sel == 1) ? g_wkw : g_wv;
    __nv_bfloat16* out = (sel == 0) ? g_qp : (sel == 1) ? g_kp : g_vp;

    __shared__ __nv_bfloat16 sW[128 * 136];
    __shared__ __nv_bfloat16 sX[32 * 136];
    int tid = threadIdx.x;

    // stage weights (bf16, padded stride 136 elems = 68 words)
    {
        const unsigned* wsrc = reinterpret_cast<const unsigned*>(wbf);
        unsigned* wdst = reinterpret_cast<unsigned*>(sW);
        for (int i = tid; i < 8192; i += 256) {
            wdst[(i >> 6) * 68 + (i & 63)] = wsrc[i];
        }
    }

    int r0 = blockIdx.x * 32;
    int l = r0 / T;
    int tbase = r0 % T;

    // LayerNorm: 8 threads per row
    {
        int row = tid >> 3, sub = tid & 7;
        int t = tbase + row;
        int n = t / chunk, rem = t % chunk;
        const float* src = x + ((size_t)(n * LTOT + l) * chunk + rem) * 128 + sub * 16;
        float v[16];
        #pragma unroll
        for (int i = 0; i < 4; i++) {
            float4 f = reinterpret_cast<const float4*>(src)[i];
            v[4 * i + 0] = f.x; v[4 * i + 1] = f.y; v[4 * i + 2] = f.z; v[4 * i + 3] = f.w;
        }
        float s = 0.f;
        #pragma unroll
        for (int i = 0; i < 16; i++) s += v[i];
        #pragma unroll
        for (int o = 1; o < 8; o <<= 1) s += __shfl_xor_sync(0xffffffffu, s, o);
        float mu = s * (1.0f / 128.0f);
        float q2 = 0.f;
        #pragma unroll
        for (int i = 0; i < 16; i++) { float d = v[i] - mu; q2 += d * d; }
        #pragma unroll
        for (int o = 1; o < 8; o <<= 1) q2 += __shfl_xor_sync(0xffffffffu, q2, o);
        float rs = rsqrtf(q2 * (1.0f / 128.0f) + 1e-5f);
        unsigned* xdst = reinterpret_cast<unsigned*>(sX) + row * 68 + sub * 8;
        #pragma unroll
        for (int i = 0; i < 8; i++) {
            int c0 = sub * 16 + 2 * i;
            float a0 = (v[2 * i] - mu) * rs * lng[c0] + lnb[c0];
            float a1 = (v[2 * i + 1] - mu) * rs * lng[c0 + 1] + lnb[c0 + 1];
            xdst[i] = pk(a0, a1);
        }
    }
    __syncthreads();

    // GEMM: warp w -> rows (w&1)*16..+16, head mh = w>>1 (cols mh*32..+32, 4 n-tiles)
    int wid = tid >> 5, lane = tid & 31, gq = lane >> 2, t4 = lane & 3;
    int mrow = (wid & 1) * 16;
    int mh = wid >> 1;
    float acc[4][4] = {};
    #pragma unroll
    for (int kk = 0; kk < 128; kk += 16) {
        unsigned a[4];
        a[0] = *reinterpret_cast<const unsigned*>(&sX[(mrow + gq) * 136 + kk + 2 * t4]);
        a[1] = *reinterpret_cast<const unsigned*>(&sX[(mrow + gq + 8) * 136 + kk + 2 * t4]);
        a[2] = *reinterpret_cast<const unsigned*>(&sX[(mrow + gq) * 136 + kk + 8 + 2 * t4]);
        a[3] = *reinterpret_cast<const unsigned*>(&sX[(mrow + gq + 8) * 136 + kk + 8 + 2 * t4]);
        #pragma unroll
        for (int nt = 0; nt < 4; nt++) {
            int o = mh * 32 + nt * 8 + gq;
            unsigned b[2];
            b[0] = *reinterpret_cast<const unsigned*>(&sW[o * 136 + kk + 2 * t4]);
            b[1] = *reinterpret_cast<const unsigned*>(&sW[o * 136 + kk + 8 + 2 * t4]);
            mma16816(acc[nt], a, b);
        }
    }

    // epilogue: +bias -> RoPE (cols j and j+16 live in acc[nt] and acc[nt+2]) -> scale -> bf16
    float sc = use_scale ? g_scales[mh] : 1.0f;
    #pragma unroll
    for (int r = 0; r < 2; r++) {
        int t = tbase + mrow + gq + 8 * r;
        __nv_bfloat16* op = out + ((size_t)(l * 4 + mh) * T + t) * 32;
        #pragma unroll
        for (int ntl = 0; ntl < 2; ntl++) {
            int jlo = ntl * 8 + 2 * t4;
            int jhi = jlo + 16;
            float plo0 = acc[ntl][2 * r + 0] + bias[mh * 32 + jlo];
            float plo1 = acc[ntl][2 * r + 1] + bias[mh * 32 + jlo + 1];
            float phi0 = acc[ntl + 2][2 * r + 0] + bias[mh * 32 + jhi];
            float phi1 = acc[ntl + 2][2 * r + 1] + bias[mh * 32 + jhi + 1];
            float y0, y1, y2, y3;
            if (use_rope) {
                float cl0 = g_cos[t * 32 + jlo],     cl1 = g_cos[t * 32 + jlo + 1];
                float sl0 = g_sin[t * 32 + jlo],     sl1 = g_sin[t * 32 + jlo + 1];
                float ch0 = g_cos[t * 32 + jhi],     ch1 = g_cos[t * 32 + jhi + 1];
                float sh0 = g_sin[t * 32 + jhi],     sh1 = g_sin[t * 32 + jhi + 1];
                y0 = plo0 * cl0 - phi0 * sl0;
                y1 = plo1 * cl1 - phi1 * sl1;
                y2 = phi0 * ch0 + plo0 * sh0;
                y3 = phi1 * ch1 + plo1 * sh1;
            } else {
                y0 = plo0; y1 = plo1; y2 = phi0; y3 = phi1;
            }
            *reinterpret_cast<unsigned*>(op + jlo) = pk(y0 * sc, y1 * sc);
            *reinterpret_cast<unsigned*>(op + jhi) = pk(y2 * sc, y3 * sc);
        }
    }
}

// ---------------- kernel 2: attention ----------------
// block = (l, m); 8 warps, each handles 48 query rows (3 tiles of 16).
__global__ __launch_bounds__(256) void attn_kernel()
{
    int bx = blockIdx.x;
    int l = bx >> 2, m = bx & 3;
    __shared__ __nv_bfloat16 sK[96 * 40];    // K[s][d], padded
    __shared__ __nv_bfloat16 sVt[32 * 104];  // V^T[d][s], padded
    int tid = threadIdx.x;

    size_t kvoff = (size_t)(l * 4 + m) * KN * 32;
    const unsigned* ks = reinterpret_cast<const unsigned*>(g_kp + kvoff);
    const unsigned* vs = reinterpret_cast<const unsigned*>(g_vp + kvoff);
    for (int i = tid; i < 1536; i += 256) {
        int s = i >> 4, j = i & 15;
        reinterpret_cast<unsigned*>(sK)[s * 20 + j] = ks[i];
        unsigned w = vs[i];
        __nv_bfloat162 h = *reinterpret_cast<__nv_bfloat162*>(&w);
        sVt[(2 * j) * 104 + s] = h.x;
        sVt[(2 * j + 1) * 104 + s] = h.y;
    }
    __syncthreads();

    int wid = tid >> 5, lane = tid & 31, g = lane >> 2, t4 = lane & 3;
    const __nv_bfloat16* qb = g_qp + (size_t)(l * 4 + m) * QN * 32;
    __nv_bfloat16* ob = g_att + (size_t)l * QN * 128 + m * 32;

    for (int mt = 0; mt < 3; mt++) {
        int tr0 = wid * 48 + mt * 16;
        float sacc[12][4] = {};
        // S = Q K^T  (scale already folded into Q)
        #pragma unroll
        for (int kk = 0; kk < 32; kk += 16) {
            unsigned a[4];
            a[0] = *reinterpret_cast<const unsigned*>(qb + (tr0 + g) * 32 + kk + 2 * t4);
            a[1] = *reinterpret_cast<const unsigned*>(qb + (tr0 + g + 8) * 32 + kk + 2 * t4);
            a[2] = *reinterpret_cast<const unsigned*>(qb + (tr0 + g) * 32 + kk + 8 + 2 * t4);
            a[3] = *reinterpret_cast<const unsigned*>(qb + (tr0 + g + 8) * 32 + kk + 8 + 2 * t4);
            #pragma unroll
            for (int nt = 0; nt < 12; nt++) {
                unsigned b[2];
                b[0] = *reinterpret_cast<const unsigned*>(&sK[(nt * 8 + g) * 40 + kk + 2 * t4]);
                b[1] = *reinterpret_cast<const unsigned*>(&sK[(nt * 8 + g) * 40 + kk + 8 + 2 * t4]);
                mma16816(sacc[nt], a, b);
            }
        }
        // softmax over 96 (row spread across the 4 quad lanes)
        float mx0 = -1e30f, mx1 = -1e30f;
        #pragma unroll
        for (int nt = 0; nt < 12; nt++) {
            mx0 = fmaxf(mx0, fmaxf(sacc[nt][0], sacc[nt][1]));
            mx1 = fmaxf(mx1, fmaxf(sacc[nt][2], sacc[nt][3]));
        }
        mx0 = fmaxf(mx0, __shfl_xor_sync(0xffffffffu, mx0, 1));
        mx0 = fmaxf(mx0, __shfl_xor_sync(0xffffffffu, mx0, 2));
        mx1 = fmaxf(mx1, __shfl_xor_sync(0xffffffffu, mx1, 1));
        mx1 = fmaxf(mx1, __shfl_xor_sync(0xffffffffu, mx1, 2));
        float sm0 = 0.f, sm1 = 0.f;
        #pragma unroll
        for (int nt = 0; nt < 12; nt++) {
            sacc[nt][0] = __expf(sacc[nt][0] - mx0);
            sacc[nt][1] = __expf(sacc[nt][1] - mx0);
            sacc[nt][2] = __expf(sacc[nt][2] - mx1);
            sacc[nt][3] = __expf(sacc[nt][3] - mx1);
            sm0 += sacc[nt][0] + sacc[nt][1];
            sm1 += sacc[nt][2] + sacc[nt][3];
        }
        sm0 += __shfl_xor_sync(0xffffffffu, sm0, 1);
        sm0 += __shfl_xor_sync(0xffffffffu, sm0, 2);
        sm1 += __shfl_xor_sync(0xffffffffu, sm1, 1);
        sm1 += __shfl_xor_sync(0xffffffffu, sm1, 2);
        float r0i = 1.0f / sm0, r1i = 1.0f / sm1;
        #pragma unroll
        for (int nt = 0; nt < 12; nt++) {
            sacc[nt][0] *= r0i; sacc[nt][1] *= r0i;
            sacc[nt][2] *= r1i; sacc[nt][3] *= r1i;
        }
        // O = P V : S-tile register layout == A-fragment layout
        float oacc[4][4] = {};
        #pragma unroll
        for (int c = 0; c < 6; c++) {
            unsigned a[4];
            a[0] = pk(sacc[2 * c][0], sacc[2 * c][1]);
            a[1] = pk(sacc[2 * c][2], sacc[2 * c][3]);
            a[2] = pk(sacc[2 * c + 1][0], sacc[2 * c + 1][1]);
            a[3] = pk(sacc[2 * c + 1][2], sacc[2 * c + 1][3]);
            #pragma unroll
            for (int nt = 0; nt < 4; nt++) {
                unsigned b[2];
                b[0] = *reinterpret_cast<const unsigned*>(&sVt[(nt * 8 + g) * 104 + c * 16 + 2 * t4]);
                b[1] = *reinterpret_cast<const unsigned*>(&sVt[(nt * 8 + g) * 104 + c * 16 + 8 + 2 * t4]);
                mma16816(oacc[nt], a, b);
            }
        }
        // write merged-head layout (l, t, m*32+j)
        #pragma unroll
        for (int nt = 0; nt < 4; nt++) {
            int col = nt * 8 + 2 * t4;
            *reinterpret_cast<unsigned*>(ob + (size_t)(tr0 + g) * 128 + col) = pk(oacc[nt][0], oacc[nt][1]);
            *reinterpret_cast<unsigned*>(ob + (size_t)(tr0 + g + 8) * 128 + col) = pk(oacc[nt][2], oacc[nt][3]);
        }
    }
}

// ---------------- kernel 3: mean over views + projection + skip ----------------
__global__ __launch_bounds__(256) void proj_kernel(
    const float* __restrict__ skip, const float* __restrict__ bproj,
    float* __restrict__ out)
{
    __shared__ __nv_bfloat16 sW[128 * 136];
    __shared__ __nv_bfloat16 sX[32 * 136];
    int tid = threadIdx.x;
    {
        const unsigned* wsrc = reinterpret_cast<const unsigned*>(g_wp);
        unsigned* wdst = reinterpret_cast<unsigned*>(sW);
        for (int i = tid; i < 8192; i += 256) {
            wdst[(i >> 6) * 68 + (i & 63)] = wsrc[i];
        }
    }
    int r0 = blockIdx.x * 32;
    {
        int row = tid >> 3, sub = tid & 7;
        int gr = r0 + row;
        int l = gr >> 6, uv = gr & 63;
        float acc[16] = {};
        #pragma unroll
        for (int n = 0; n < 6; n++) {
            const __nv_bfloat16* src = g_att + ((size_t)(l * QN + n * 64 + uv)) * 128 + sub * 16;
            #pragma unroll
            for (int i = 0; i < 8; i++) {
                __nv_bfloat162 h = reinterpret_cast<const __nv_bfloat162*>(src)[i];
                acc[2 * i] += __bfloat162float(h.x);
                acc[2 * i + 1] += __bfloat162float(h.y);
            }
        }
        unsigned* xdst = reinterpret_cast<unsigned*>(sX) + row * 68 + sub * 8;
        #pragma unroll
        for (int i = 0; i < 8; i++)
            xdst[i] = pk(acc[2 * i] * (1.0f / 6.0f), acc[2 * i + 1] * (1.0f / 6.0f));
    }
    __syncthreads();

    int wid = tid >> 5, lane = tid & 31, gq = lane >> 2, t4 = lane & 3;
    int mrow = (wid & 1) * 16, cw = (wid >> 1) * 32;
    float acc[4][4] = {};
    #pragma unroll
    for (int kk = 0; kk < 128; kk += 16) {
        unsigned a[4];
        a[0] = *reinterpret_cast<const unsigned*>(&sX[(mrow + gq) * 136 + kk + 2 * t4]);
        a[1] = *reinterpret_cast<const unsigned*>(&sX[(mrow + gq + 8) * 136 + kk + 2 * t4]);
        a[2] = *reinterpret_cast<const unsigned*>(&sX[(mrow + gq) * 136 + kk + 8 + 2 * t4]);
        a[3] = *reinterpret_cast<const unsigned*>(&sX[(mrow + gq + 8) * 136 + kk + 8 + 2 * t4]);
        #pragma unroll
        for (int nt = 0; nt < 4; nt++) {
            int o = cw + nt * 8 + gq;
            unsigned b[2];
            b[0] = *reinterpret_cast<const unsigned*>(&sW[o * 136 + kk + 2 * t4]);
            b[1] = *reinterpret_cast<const unsigned*>(&sW[o * 136 + kk + 8 + 2 * t4]);
            mma16816(acc[nt], a, b);
        }
    }
    #pragma unroll
    for (int nt = 0; nt < 4; nt++) {
        int col = cw + nt * 8 + 2 * t4;
        #pragma unroll
        for (int r = 0; r < 2; r++) {
            int rowg = r0 + mrow + gq + 8 * r;
            float2 sk = *reinterpret_cast<const float2*>(skip + (size_t)rowg * 128 + col);
            float2 o2;
            o2.x = acc[nt][2 * r] + bproj[col] + sk.x;
            o2.y = acc[nt][2 * r + 1] + bproj[col + 1] + sk.y;
            *reinterpret_cast<float2*>(out + (size_t)rowg * 128 + col) = o2;
        }
    }
}

// ---------------- launch ----------------
extern "C" void kernel_launch(void* const* d_in, const int* in_sizes, int n_in,
                              void* d_out, int out_size) {
    const float* q     = (const float*)d_in[0];
    const float* k     = (const float*)d_in[1];
    const float* v     = (const float*)d_in[2];
    const float* skip  = (const float*)d_in[3];
    const float* freqs = (const float*)d_in[4];
    const float* gate  = (const float*)d_in[5];
    const float* lnqg  = (const float*)d_in[6];
    const float* lnqb  = (const float*)d_in[7];
    const float* lnkg  = (const float*)d_in[8];
    const float* lnkb  = (const float*)d_in[9];
    const float* lnvg  = (const float*)d_in[10];
    const float* lnvb  = (const float*)d_in[11];
    const float* wq    = (const float*)d_in[12];
    const float* bq    = (const float*)d_in[13];
    const float* wk    = (const float*)d_in[14];
    const float* bk    = (const float*)d_in[15];
    const float* wv    = (const float*)d_in[16];
    const float* bv    = (const float*)d_in[17];
    const float* wproj = (const float*)d_in[18];
    const float* bproj = (const float*)d_in[19];
    const float* als   = (const float*)d_in[20];
    float* out = (float*)d_out;

    prep_const_kernel<<<305, 256>>>(wq, wk, wv, wproj, freqs, gate, als);
    prep_qkv_kernel<<<(LTOT * QN) / 32, 256>>>(q, lnqg, lnqb, bq, QN, 64, 1, 1, 0);
    prep_qkv_kernel<<<(LTOT * KN) / 32, 256>>>(k, lnkg, lnkb, bk, KN, 16, 1, 0, 1);
    prep_qkv_kernel<<<(LTOT * KN) / 32, 256>>>(v, lnvg, lnvb, bv, KN, 16, 0, 0, 2);
    attn_kernel<<<LTOT * 4, 256>>>();
    proj_kernel<<<(LTOT * 64) / 32, 256>>>(skip, bproj, out);
}

// round 3
// speedup vs baseline: 1.0429x; 1.0429x over previous
#include <cuda_runtime.h>
#include <cuda_bf16.h>
#include <math.h>

// ---------------- problem constants ----------------
// B=1, N=6, X=Y=25 (L=625), W1=W2=8 (Qn=384), w1=w2=4 (Kn=96), D=128, M=4 heads, dh=32

#define LTOT 625
#define QN   384
#define KN   96
#define GRID_P 592

// ---------------- device scratch (no allocs allowed) ----------------
__device__ __nv_bfloat16 g_qp[(size_t)LTOT * 4 * QN * 32];   // (l, m, t, dh)
__device__ __nv_bfloat16 g_kp[(size_t)LTOT * 4 * KN * 32];
__device__ __nv_bfloat16 g_vp[(size_t)LTOT * 4 * KN * 32];
__device__ __nv_bfloat16 g_att[(size_t)LTOT * QN * 128];     // (l, t, m*32+j)
__device__ __nv_bfloat16 g_wq[16384];
__device__ __nv_bfloat16 g_wkw[16384];
__device__ __nv_bfloat16 g_wv[16384];
__device__ __nv_bfloat16 g_wp[16384];
__device__ float g_cos[QN * 32];
__device__ float g_sin[QN * 32];
__device__ float g_scales[4];

// ---------------- helpers ----------------
__device__ __forceinline__ unsigned pk(float a, float b) {
    __nv_bfloat162 h = __floats2bfloat162_rn(a, b);
    return *reinterpret_cast<unsigned*>(&h);
}
__device__ __forceinline__ unsigned ssa(const void* p) {
    return (unsigned)__cvta_generic_to_shared(p);
}
__device__ __forceinline__ void ldsm4(unsigned r[4], unsigned addr) {
    asm volatile("ldmatrix.sync.aligned.m8n8.x4.shared.b16 {%0,%1,%2,%3}, [%4];\n"
                 : "=r"(r[0]), "=r"(r[1]), "=r"(r[2]), "=r"(r[3]) : "r"(addr));
}
// mma.sync m16n8k16 row.col f32.bf16.bf16.f32
__device__ __forceinline__ void mma16816(float c[4], const unsigned a[4], const unsigned b[2]) {
    asm volatile(
        "mma.sync.aligned.m16n8k16.row.col.f32.bf16.bf16.f32 "
        "{%0,%1,%2,%3}, {%4,%5,%6,%7}, {%8,%9}, {%0,%1,%2,%3};\n"
        : "+f"(c[0]), "+f"(c[1]), "+f"(c[2]), "+f"(c[3])
        : "r"(a[0]), "r"(a[1]), "r"(a[2]), "r"(a[3]), "r"(b[0]), "r"(b[1]));
}

// ---------------- kernel 0: constants prep ----------------
__global__ __launch_bounds__(256) void prep_const_kernel(
    const float* __restrict__ wq, const float* __restrict__ wk,
    const float* __restrict__ wv, const float* __restrict__ wp,
    const float* __restrict__ freqs, const float* __restrict__ gate,
    const float* __restrict__ als)
{
    int idx = blockIdx.x * 256 + threadIdx.x;
    if (idx < 16384) {
        g_wq[idx] = __float2bfloat16(wq[idx]);
    } else if (idx < 32768) {
        g_wkw[idx - 16384] = __float2bfloat16(wk[idx - 16384]);
    } else if (idx < 49152) {
        g_wv[idx - 32768] = __float2bfloat16(wv[idx - 32768]);
    } else if (idx < 65536) {
        g_wp[idx - 49152] = __float2bfloat16(wp[idx - 49152]);
    } else if (idx < 65536 + QN * 32) {
        int j = idx - 65536;
        float f = freqs[j];            // freqs is (400,32) row-major, t<384 prefix
        g_cos[j] = cosf(f);
        g_sin[j] = sinf(f);
    } else if (idx < 65536 + QN * 32 + 4) {
        int m = idx - (65536 + QN * 32);
        float temp = als[m] - 0.5f * logf(32.0f);   // als + log(dh^-0.5)
        float ga = fminf(fmaxf(gate[m], 0.0f), 1.0f);
        g_scales[m] = temp * ga;
    }
}

// ---------------- kernel 1: gather + LayerNorm + Linear + RoPE (persistent) ----------------
// chunk of 32 rows; weights staged ONCE per block; ldmatrix fragment loads.
__global__ __launch_bounds__(256) void prep_qkv_kernel(
    const float* __restrict__ x, const float* __restrict__ lng,
    const float* __restrict__ lnb, const float* __restrict__ bias,
    int T, int chunk, int use_rope, int use_scale, int sel)
{
    const __nv_bfloat16* wbf = (sel == 0) ? g_wq : (sel == 1) ? g_wkw : g_wv;
    __nv_bfloat16* out = (sel == 0) ? g_qp : (sel == 1) ? g_kp : g_vp;

    __shared__ __nv_bfloat16 sW[128 * 136];
    __shared__ __nv_bfloat16 sX[32 * 136];
    int tid = threadIdx.x;

    // stage weights once (bf16, padded stride 136 elems = 68 words)
    {
        const unsigned* wsrc = reinterpret_cast<const unsigned*>(wbf);
        unsigned* wdst = reinterpret_cast<unsigned*>(sW);
        for (int i = tid; i < 8192; i += 256) {
            wdst[(i >> 6) * 68 + (i & 63)] = wsrc[i];
        }
    }

    int wid = tid >> 5, lane = tid & 31, gq = lane >> 2, t4 = lane & 3;
    int mrow = (wid & 1) * 16;
    int mh = wid >> 1;
    // ldmatrix lane-address bases (element offsets; byte = *2)
    unsigned abase = ssa(&sX[(mrow + (lane & 15)) * 136 + ((lane >> 4) << 3)]);
    unsigned bbase0 = ssa(&sW[(mh * 32 + ((lane >> 4) * 8) + (lane & 7)) * 136 + (((lane >> 3) & 1) << 3)]);
    unsigned bbase1 = bbase0 + 16 * 136 * 2;   // nt pair {2,3} is +16 output rows

    int nch = (LTOT * T) / 32;
    for (int c = blockIdx.x; c < nch; c += gridDim.x) {
        int r0 = c * 32;
        int l = r0 / T;
        int tbase = r0 % T;

        // LayerNorm: 8 threads per row
        {
            int row = tid >> 3, sub = tid & 7;
            int t = tbase + row;
            int n = t / chunk, rem = t % chunk;
            const float* src = x + ((size_t)(n * LTOT + l) * chunk + rem) * 128 + sub * 16;
            float v[16];
            #pragma unroll
            for (int i = 0; i < 4; i++) {
                float4 f = reinterpret_cast<const float4*>(src)[i];
                v[4 * i + 0] = f.x; v[4 * i + 1] = f.y; v[4 * i + 2] = f.z; v[4 * i + 3] = f.w;
            }
            float s = 0.f;
            #pragma unroll
            for (int i = 0; i < 16; i++) s += v[i];
            #pragma unroll
            for (int o = 1; o < 8; o <<= 1) s += __shfl_xor_sync(0xffffffffu, s, o);
            float mu = s * (1.0f / 128.0f);
            float q2 = 0.f;
            #pragma unroll
            for (int i = 0; i < 16; i++) { float d = v[i] - mu; q2 += d * d; }
            #pragma unroll
            for (int o = 1; o < 8; o <<= 1) q2 += __shfl_xor_sync(0xffffffffu, q2, o);
            float rs = rsqrtf(q2 * (1.0f / 128.0f) + 1e-5f);
            unsigned* xdst = reinterpret_cast<unsigned*>(sX) + row * 68 + sub * 8;
            #pragma unroll
            for (int i = 0; i < 8; i++) {
                int c0 = sub * 16 + 2 * i;
                float a0 = (v[2 * i] - mu) * rs * lng[c0] + lnb[c0];
                float a1 = (v[2 * i + 1] - mu) * rs * lng[c0 + 1] + lnb[c0 + 1];
                xdst[i] = pk(a0, a1);
            }
        }
        __syncthreads();

        // GEMM via ldmatrix
        float acc[4][4] = {};
        #pragma unroll
        for (int kk = 0; kk < 128; kk += 16) {
            unsigned a[4], b01[4], b23[4];
            ldsm4(a, abase + kk * 2);
            ldsm4(b01, bbase0 + kk * 2);
            ldsm4(b23, bbase1 + kk * 2);
            mma16816(acc[0], a, &b01[0]);
            mma16816(acc[1], a, &b01[2]);
            mma16816(acc[2], a, &b23[0]);
            mma16816(acc[3], a, &b23[2]);
        }

        // epilogue: +bias -> RoPE (cols j, j+16 in acc[nt], acc[nt+2]) -> scale -> bf16
        float sc = use_scale ? g_scales[mh] : 1.0f;
        #pragma unroll
        for (int r = 0; r < 2; r++) {
            int t = tbase + mrow + gq + 8 * r;
            __nv_bfloat16* op = out + ((size_t)(l * 4 + mh) * T + t) * 32;
            #pragma unroll
            for (int ntl = 0; ntl < 2; ntl++) {
                int jlo = ntl * 8 + 2 * t4;
                int jhi = jlo + 16;
                float plo0 = acc[ntl][2 * r + 0] + bias[mh * 32 + jlo];
                float plo1 = acc[ntl][2 * r + 1] + bias[mh * 32 + jlo + 1];
                float phi0 = acc[ntl + 2][2 * r + 0] + bias[mh * 32 + jhi];
                float phi1 = acc[ntl + 2][2 * r + 1] + bias[mh * 32 + jhi + 1];
                float y0, y1, y2, y3;
                if (use_rope) {
                    float cl0 = g_cos[t * 32 + jlo],     cl1 = g_cos[t * 32 + jlo + 1];
                    float sl0 = g_sin[t * 32 + jlo],     sl1 = g_sin[t * 32 + jlo + 1];
                    float ch0 = g_cos[t * 32 + jhi],     ch1 = g_cos[t * 32 + jhi + 1];
                    float sh0 = g_sin[t * 32 + jhi],     sh1 = g_sin[t * 32 + jhi + 1];
                    y0 = plo0 * cl0 - phi0 * sl0;
                    y1 = plo1 * cl1 - phi1 * sl1;
                    y2 = phi0 * ch0 + plo0 * sh0;
                    y3 = phi1 * ch1 + plo1 * sh1;
                } else {
                    y0 = plo0; y1 = plo1; y2 = phi0; y3 = phi1;
                }
                *reinterpret_cast<unsigned*>(op + jlo) = pk(y0 * sc, y1 * sc);
                *reinterpret_cast<unsigned*>(op + jhi) = pk(y2 * sc, y3 * sc);
            }
        }
        __syncthreads();   // protect sX before next iteration overwrites it
    }
}

// ---------------- kernel 2: attention ----------------
// block = (l, m); 8 warps, each handles 48 query rows (3 tiles of 16).
// Q staged in smem (coalesced), all fragments via ldmatrix.
__global__ __launch_bounds__(256) void attn_kernel()
{
    int bx = blockIdx.x;
    int l = bx >> 2, m = bx & 3;
    __shared__ __nv_bfloat16 sQ[QN * 40];    // Q[t][d], padded (20 words/row)
    __shared__ __nv_bfloat16 sK[96 * 40];    // K[s][d], padded
    __shared__ __nv_bfloat16 sVt[32 * 104];  // V^T[d][s], padded (52 words/row)
    int tid = threadIdx.x;

    size_t kvoff = (size_t)(l * 4 + m) * KN * 32;
    const unsigned* qs = reinterpret_cast<const unsigned*>(g_qp + (size_t)(l * 4 + m) * QN * 32);
    const unsigned* ks = reinterpret_cast<const unsigned*>(g_kp + kvoff);
    const unsigned* vs = reinterpret_cast<const unsigned*>(g_vp + kvoff);
    for (int i = tid; i < 6144; i += 256) {
        reinterpret_cast<unsigned*>(sQ)[(i >> 4) * 20 + (i & 15)] = qs[i];
    }
    for (int i = tid; i < 1536; i += 256) {
        int s = i >> 4, j = i & 15;
        reinterpret_cast<unsigned*>(sK)[s * 20 + j] = ks[i];
        unsigned w = vs[i];
        __nv_bfloat162 h = *reinterpret_cast<__nv_bfloat162*>(&w);
        sVt[(2 * j) * 104 + s] = h.x;
        sVt[(2 * j + 1) * 104 + s] = h.y;
    }
    __syncthreads();

    int wid = tid >> 5, lane = tid & 31, g = lane >> 2, t4 = lane & 3;
    __nv_bfloat16* ob = g_att + (size_t)l * QN * 128 + m * 32;

    // ldmatrix lane bases
    unsigned kb[6], vb[2];
    #pragma unroll
    for (int p = 0; p < 6; p++)
        kb[p] = ssa(&sK[((2 * p + (lane >> 4)) * 8 + (lane & 7)) * 40 + (((lane >> 3) & 1) << 3)]);
    #pragma unroll
    for (int p = 0; p < 2; p++)
        vb[p] = ssa(&sVt[((2 * p + (lane >> 4)) * 8 + (lane & 7)) * 104 + (((lane >> 3) & 1) << 3)]);

    for (int mt = 0; mt < 3; mt++) {
        int tr0 = wid * 48 + mt * 16;
        unsigned abase = ssa(&sQ[(tr0 + (lane & 15)) * 40 + ((lane >> 4) << 3)]);
        float sacc[12][4] = {};
        // S = Q K^T  (scale already folded into Q)
        #pragma unroll
        for (int kk = 0; kk < 32; kk += 16) {
            unsigned a[4];
            ldsm4(a, abase + kk * 2);
            #pragma unroll
            for (int p = 0; p < 6; p++) {
                unsigned b[4];
                ldsm4(b, kb[p] + kk * 2);
                mma16816(sacc[2 * p], a, &b[0]);
                mma16816(sacc[2 * p + 1], a, &b[2]);
            }
        }
        // softmax over 96 (row spread across the 4 quad lanes)
        float mx0 = -1e30f, mx1 = -1e30f;
        #pragma unroll
        for (int nt = 0; nt < 12; nt++) {
            mx0 = fmaxf(mx0, fmaxf(sacc[nt][0], sacc[nt][1]));
            mx1 = fmaxf(mx1, fmaxf(sacc[nt][2], sacc[nt][3]));
        }
        mx0 = fmaxf(mx0, __shfl_xor_sync(0xffffffffu, mx0, 1));
        mx0 = fmaxf(mx0, __shfl_xor_sync(0xffffffffu, mx0, 2));
        mx1 = fmaxf(mx1, __shfl_xor_sync(0xffffffffu, mx1, 1));
        mx1 = fmaxf(mx1, __shfl_xor_sync(0xffffffffu, mx1, 2));
        float sm0 = 0.f, sm1 = 0.f;
        #pragma unroll
        for (int nt = 0; nt < 12; nt++) {
            sacc[nt][0] = __expf(sacc[nt][0] - mx0);
            sacc[nt][1] = __expf(sacc[nt][1] - mx0);
            sacc[nt][2] = __expf(sacc[nt][2] - mx1);
            sacc[nt][3] = __expf(sacc[nt][3] - mx1);
            sm0 += sacc[nt][0] + sacc[nt][1];
            sm1 += sacc[nt][2] + sacc[nt][3];
        }
        sm0 += __shfl_xor_sync(0xffffffffu, sm0, 1);
        sm0 += __shfl_xor_sync(0xffffffffu, sm0, 2);
        sm1 += __shfl_xor_sync(0xffffffffu, sm1, 1);
        sm1 += __shfl_xor_sync(0xffffffffu, sm1, 2);
        float r0i = 1.0f / sm0, r1i = 1.0f / sm1;
        #pragma unroll
        for (int nt = 0; nt < 12; nt++) {
            sacc[nt][0] *= r0i; sacc[nt][1] *= r0i;
            sacc[nt][2] *= r1i; sacc[nt][3] *= r1i;
        }
        // O = P V : S-tile register layout == A-fragment layout
        float oacc[4][4] = {};
        #pragma unroll
        for (int c = 0; c < 6; c++) {
            unsigned a[4];
            a[0] = pk(sacc[2 * c][0], sacc[2 * c][1]);
            a[1] = pk(sacc[2 * c][2], sacc[2 * c][3]);
            a[2] = pk(sacc[2 * c + 1][0], sacc[2 * c + 1][1]);
            a[3] = pk(sacc[2 * c + 1][2], sacc[2 * c + 1][3]);
            #pragma unroll
            for (int p = 0; p < 2; p++) {
                unsigned b[4];
                ldsm4(b, vb[p] + c * 32);
                mma16816(oacc[2 * p], a, &b[0]);
                mma16816(oacc[2 * p + 1], a, &b[2]);
            }
        }
        // write merged-head layout (l, t, m*32+j)
        #pragma unroll
        for (int nt = 0; nt < 4; nt++) {
            int col = nt * 8 + 2 * t4;
            *reinterpret_cast<unsigned*>(ob + (size_t)(tr0 + g) * 128 + col) = pk(oacc[nt][0], oacc[nt][1]);
            *reinterpret_cast<unsigned*>(ob + (size_t)(tr0 + g + 8) * 128 + col) = pk(oacc[nt][2], oacc[nt][3]);
        }
    }
}

// ---------------- kernel 3: mean over views + projection + skip (persistent) ----------------
__global__ __launch_bounds__(256) void proj_kernel(
    const float* __restrict__ skip, const float* __restrict__ bproj,
    float* __restrict__ out)
{
    __shared__ __nv_bfloat16 sW[128 * 136];
    __shared__ __nv_bfloat16 sX[32 * 136];
    int tid = threadIdx.x;
    {
        const unsigned* wsrc = reinterpret_cast<const unsigned*>(g_wp);
        unsigned* wdst = reinterpret_cast<unsigned*>(sW);
        for (int i = tid; i < 8192; i += 256) {
            wdst[(i >> 6) * 68 + (i & 63)] = wsrc[i];
        }
    }
    int wid = tid >> 5, lane = tid & 31, gq = lane >> 2, t4 = lane & 3;
    int mrow = (wid & 1) * 16, cw = (wid >> 1) * 32;
    unsigned abase = ssa(&sX[(mrow + (lane & 15)) * 136 + ((lane >> 4) << 3)]);
    unsigned bbase0 = ssa(&sW[(cw + ((lane >> 4) * 8) + (lane & 7)) * 136 + (((lane >> 3) & 1) << 3)]);
    unsigned bbase1 = bbase0 + 16 * 136 * 2;

    int nch = (LTOT * 64) / 32;
    for (int c = blockIdx.x; c < nch; c += gridDim.x) {
        int r0 = c * 32;
        {
            int row = tid >> 3, sub = tid & 7;
            int gr = r0 + row;
            int l = gr >> 6, uv = gr & 63;
            float acc[16] = {};
            #pragma unroll
            for (int n = 0; n < 6; n++) {
                const __nv_bfloat16* src = g_att + ((size_t)(l * QN + n * 64 + uv)) * 128 + sub * 16;
                #pragma unroll
                for (int i = 0; i < 8; i++) {
                    __nv_bfloat162 h = reinterpret_cast<const __nv_bfloat162*>(src)[i];
                    acc[2 * i] += __bfloat162float(h.x);
                    acc[2 * i + 1] += __bfloat162float(h.y);
                }
            }
            unsigned* xdst = reinterpret_cast<unsigned*>(sX) + row * 68 + sub * 8;
            #pragma unroll
            for (int i = 0; i < 8; i++)
                xdst[i] = pk(acc[2 * i] * (1.0f / 6.0f), acc[2 * i + 1] * (1.0f / 6.0f));
        }
        __syncthreads();

        float acc[4][4] = {};
        #pragma unroll
        for (int kk = 0; kk < 128; kk += 16) {
            unsigned a[4], b01[4], b23[4];
            ldsm4(a, abase + kk * 2);
            ldsm4(b01, bbase0 + kk * 2);
            ldsm4(b23, bbase1 + kk * 2);
            mma16816(acc[0], a, &b01[0]);
            mma16816(acc[1], a, &b01[2]);
            mma16816(acc[2], a, &b23[0]);
            mma16816(acc[3], a, &b23[2]);
        }
        #pragma unroll
        for (int nt = 0; nt < 4; nt++) {
            int col = cw + nt * 8 + 2 * t4;
            #pragma unroll
            for (int r = 0; r < 2; r++) {
                int rowg = r0 + mrow + gq + 8 * r;
                float2 sk = *reinterpret_cast<const float2*>(skip + (size_t)rowg * 128 + col);
                float2 o2;
                o2.x = acc[nt][2 * r] + bproj[col] + sk.x;
                o2.y = acc[nt][2 * r + 1] + bproj[col + 1] + sk.y;
                *reinterpret_cast<float2*>(out + (size_t)rowg * 128 + col) = o2;
            }
        }
        __syncthreads();
    }
}

// ---------------- launch ----------------
extern "C" void kernel_launch(void* const* d_in, const int* in_sizes, int n_in,
                              void* d_out, int out_size) {
    const float* q     = (const float*)d_in[0];
    const float* k     = (const float*)d_in[1];
    const float* v     = (const float*)d_in[2];
    const float* skip  = (const float*)d_in[3];
    const float* freqs = (const float*)d_in[4];
    const float* gate  = (const float*)d_in[5];
    const float* lnqg  = (const float*)d_in[6];
    const float* lnqb  = (const float*)d_in[7];
    const float* lnkg  = (const float*)d_in[8];
    const float* lnkb  = (const float*)d_in[9];
    const float* lnvg  = (const float*)d_in[10];
    const float* lnvb  = (const float*)d_in[11];
    const float* wq    = (const float*)d_in[12];
    const float* bq    = (const float*)d_in[13];
    const float* wk    = (const float*)d_in[14];
    const float* bk    = (const float*)d_in[15];
    const float* wv    = (const float*)d_in[16];
    const float* bv    = (const float*)d_in[17];
    const float* wproj = (const float*)d_in[18];
    const float* bproj = (const float*)d_in[19];
    const float* als   = (const float*)d_in[20];
    float* out = (float*)d_out;

    prep_const_kernel<<<305, 256>>>(wq, wk, wv, wproj, freqs, gate, als);
    prep_qkv_kernel<<<GRID_P, 256>>>(q, lnqg, lnqb, bq, QN, 64, 1, 1, 0);
    prep_qkv_kernel<<<GRID_P, 256>>>(k, lnkg, lnkb, bk, KN, 16, 1, 0, 1);
    prep_qkv_kernel<<<GRID_P, 256>>>(v, lnvg, lnvb, bv, KN, 16, 0, 0, 2);
    attn_kernel<<<LTOT * 4, 256>>>();
    proj_kernel<<<GRID_P, 256>>>(skip, bproj, out);
}

// round 4
// speedup vs baseline: 1.1762x; 1.1279x over previous
#include <cuda_runtime.h>
#include <cuda_bf16.h>
#include <math.h>

// ---------------- problem constants ----------------
// B=1, N=6, X=Y=25 (L=625), W1=W2=8 (Qn=384), w1=w2=4 (Kn=96), D=128, M=4 heads, dh=32

#define LTOT 625
#define QN   384
#define KN   96

// ---------------- device constants (converted once) ----------------
__device__ __nv_bfloat16 g_wq[16384];
__device__ __nv_bfloat16 g_wkw[16384];
__device__ __nv_bfloat16 g_wv[16384];
__device__ __nv_bfloat16 g_wp[16384];
__device__ float g_cos[QN * 32];
__device__ float g_sin[QN * 32];
__device__ float g_scales[4];

// ---------------- helpers ----------------
__device__ __forceinline__ unsigned pk(float a, float b) {
    __nv_bfloat162 h = __floats2bfloat162_rn(a, b);
    return *reinterpret_cast<unsigned*>(&h);
}
__device__ __forceinline__ unsigned ssa(const void* p) {
    return (unsigned)__cvta_generic_to_shared(p);
}
__device__ __forceinline__ void ldsm4(unsigned r[4], unsigned addr) {
    asm volatile("ldmatrix.sync.aligned.m8n8.x4.shared.b16 {%0,%1,%2,%3}, [%4];\n"
                 : "=r"(r[0]), "=r"(r[1]), "=r"(r[2]), "=r"(r[3]) : "r"(addr));
}
__device__ __forceinline__ void mma16816(float c[4], const unsigned a[4], const unsigned b[2]) {
    asm volatile(
        "mma.sync.aligned.m16n8k16.row.col.f32.bf16.bf16.f32 "
        "{%0,%1,%2,%3}, {%4,%5,%6,%7}, {%8,%9}, {%0,%1,%2,%3};\n"
        : "+f"(c[0]), "+f"(c[1]), "+f"(c[2]), "+f"(c[3])
        : "r"(a[0]), "r"(a[1]), "r"(a[2]), "r"(a[3]), "r"(b[0]), "r"(b[1]));
}

// ---------------- kernel 0: constants prep ----------------
__global__ __launch_bounds__(256) void prep_const_kernel(
    const float* __restrict__ wq, const float* __restrict__ wk,
    const float* __restrict__ wv, const float* __restrict__ wp,
    const float* __restrict__ freqs, const float* __restrict__ gate,
    const float* __restrict__ als)
{
    int idx = blockIdx.x * 256 + threadIdx.x;
    if (idx < 16384) {
        g_wq[idx] = __float2bfloat16(wq[idx]);
    } else if (idx < 32768) {
        g_wkw[idx - 16384] = __float2bfloat16(wk[idx - 16384]);
    } else if (idx < 49152) {
        g_wv[idx - 32768] = __float2bfloat16(wv[idx - 32768]);
    } else if (idx < 65536) {
        g_wp[idx - 49152] = __float2bfloat16(wp[idx - 49152]);
    } else if (idx < 65536 + QN * 32) {
        int j = idx - 65536;
        float f = freqs[j];            // (400,32) row-major, t<384 prefix
        g_cos[j] = cosf(f);
        g_sin[j] = sinf(f);
    } else if (idx < 65536 + QN * 32 + 4) {
        int m = idx - (65536 + QN * 32);
        float temp = als[m] - 0.5f * logf(32.0f);   // als + log(dh^-0.5)
        float ga = fminf(fmaxf(gate[m], 0.0f), 1.0f);
        g_scales[m] = temp * ga;
    }
}

// ---------------- fused kernel: one block per l-tile ----------------
// smem element offsets (bf16 elems):
//   sK  : 4 heads * 96 * 40            = 15360
//   sVt : 4 heads * 32 * 104           = 13312
//   sW0 : 128 * 136                    = 17408
//   sW1 : 128 * 136                    = 17408
//   sX  : 64 * 136 (staging; later sO) =  8704
// total 72192 elems = 144384 bytes
#define E_K   0
#define E_VT  15360
#define E_W0  28672
#define E_W1  46080
#define E_X   63488
#define SMEM_ELEMS 72192
#define SMEM_BYTES (SMEM_ELEMS * 2)

__global__ __launch_bounds__(512, 1) void fused_kernel(
    const float* __restrict__ q, const float* __restrict__ k,
    const float* __restrict__ v, const float* __restrict__ skip,
    const float* __restrict__ lnqg, const float* __restrict__ lnqb,
    const float* __restrict__ lnkg, const float* __restrict__ lnkb,
    const float* __restrict__ lnvg, const float* __restrict__ lnvb,
    const float* __restrict__ bq, const float* __restrict__ bk,
    const float* __restrict__ bv, const float* __restrict__ bproj,
    float* __restrict__ out)
{
    extern __shared__ __nv_bfloat16 sm[];
    __nv_bfloat16* sK  = sm + E_K;
    __nv_bfloat16* sVt = sm + E_VT;
    __nv_bfloat16* sW0 = sm + E_W0;
    __nv_bfloat16* sW1 = sm + E_W1;
    __nv_bfloat16* sX  = sm + E_X;

    int l = blockIdx.x;
    int tid = threadIdx.x;
    int g = tid >> 8;              // thread group (0/1), 256 threads each
    int tl = tid & 255;
    int wid = tid >> 5, lane = tid & 31;
    int wg = wid & 7;              // warp index within group
    int gq = lane >> 2, t4 = lane & 3;

    int mrow = (wg & 1) * 16;      // row-half within 32-row chunk
    int mh = wg >> 1;              // head

    __nv_bfloat16* sXg = sX + g * 32 * 136;
    unsigned abaseA = ssa(&sXg[(mrow + (lane & 15)) * 136 + ((lane >> 4) << 3)]);

    // ---- load wk -> sW0, wv -> sW1 ----
    {
        const unsigned* s0 = reinterpret_cast<const unsigned*>(g_wkw);
        const unsigned* s1 = reinterpret_cast<const unsigned*>(g_wv);
        unsigned* d0 = reinterpret_cast<unsigned*>(sW0);
        unsigned* d1 = reinterpret_cast<unsigned*>(sW1);
        for (int i = tid; i < 8192; i += 512) {
            int o = (i >> 6) * 68 + (i & 63);
            d0[o] = s0[i];
            d1[o] = s1[i];
        }
    }
    __syncthreads();

    // =========================== Phase A: K (group 0) / V (group 1) ===========================
    {
        const float* xin  = g ? v : k;
        const float* lng  = g ? lnvg : lnkg;
        const float* lnb_ = g ? lnvb : lnkb;
        const float* bia  = g ? bv : bk;
        __nv_bfloat16* sWg = g ? sW1 : sW0;
        unsigned bbase0 = ssa(&sWg[(mh * 32 + ((lane >> 4) * 8) + (lane & 7)) * 136 + (((lane >> 3) & 1) << 3)]);
        unsigned bbase1 = bbase0 + 16 * 136 * 2;

        for (int c = 0; c < 3; c++) {
            // LayerNorm 32 rows (8 threads/row within the group)
            {
                int row = tl >> 3, sub = tl & 7;
                int t = c * 32 + row;
                int n = t >> 4, rem = t & 15;
                const float* src = xin + ((size_t)(n * LTOT + l) * 16 + rem) * 128 + sub * 16;
                float vv[16];
                #pragma unroll
                for (int i = 0; i < 4; i++) {
                    float4 f = reinterpret_cast<const float4*>(src)[i];
                    vv[4 * i] = f.x; vv[4 * i + 1] = f.y; vv[4 * i + 2] = f.z; vv[4 * i + 3] = f.w;
                }
                float s = 0.f;
                #pragma unroll
                for (int i = 0; i < 16; i++) s += vv[i];
                #pragma unroll
                for (int o = 1; o < 8; o <<= 1) s += __shfl_xor_sync(0xffffffffu, s, o);
                float mu = s * (1.0f / 128.0f);
                float q2 = 0.f;
                #pragma unroll
                for (int i = 0; i < 16; i++) { float d = vv[i] - mu; q2 += d * d; }
                #pragma unroll
                for (int o = 1; o < 8; o <<= 1) q2 += __shfl_xor_sync(0xffffffffu, q2, o);
                float rs = rsqrtf(q2 * (1.0f / 128.0f) + 1e-5f);
                unsigned* xdst = reinterpret_cast<unsigned*>(sXg) + row * 68 + sub * 8;
                #pragma unroll
                for (int i = 0; i < 8; i++) {
                    int c0 = sub * 16 + 2 * i;
                    float a0 = (vv[2 * i] - mu) * rs * lng[c0] + lnb_[c0];
                    float a1 = (vv[2 * i + 1] - mu) * rs * lng[c0 + 1] + lnb_[c0 + 1];
                    xdst[i] = pk(a0, a1);
                }
            }
            __syncthreads();

            float acc[4][4] = {};
            #pragma unroll
            for (int kk = 0; kk < 128; kk += 16) {
                unsigned a[4], b01[4], b23[4];
                ldsm4(a, abaseA + kk * 2);
                ldsm4(b01, bbase0 + kk * 2);
                ldsm4(b23, bbase1 + kk * 2);
                mma16816(acc[0], a, &b01[0]);
                mma16816(acc[1], a, &b01[2]);
                mma16816(acc[2], a, &b23[0]);
                mma16816(acc[3], a, &b23[2]);
            }

            if (g == 0) {
                // K: +bias -> RoPE -> sK[(mh*96+t)*40 + j]
                #pragma unroll
                for (int r = 0; r < 2; r++) {
                    int t = c * 32 + mrow + gq + 8 * r;
                    __nv_bfloat16* op = sK + (mh * 96 + t) * 40;
                    #pragma unroll
                    for (int ntl = 0; ntl < 2; ntl++) {
                        int jlo = ntl * 8 + 2 * t4;
                        int jhi = jlo + 16;
                        float2 blo = *reinterpret_cast<const float2*>(&bia[mh * 32 + jlo]);
                        float2 bhi = *reinterpret_cast<const float2*>(&bia[mh * 32 + jhi]);
                        float plo0 = acc[ntl][2 * r] + blo.x;
                        float plo1 = acc[ntl][2 * r + 1] + blo.y;
                        float phi0 = acc[ntl + 2][2 * r] + bhi.x;
                        float phi1 = acc[ntl + 2][2 * r + 1] + bhi.y;
                        float2 cl = *reinterpret_cast<const float2*>(&g_cos[t * 32 + jlo]);
                        float2 sl = *reinterpret_cast<const float2*>(&g_sin[t * 32 + jlo]);
                        float2 ch = *reinterpret_cast<const float2*>(&g_cos[t * 32 + jhi]);
                        float2 sh = *reinterpret_cast<const float2*>(&g_sin[t * 32 + jhi]);
                        float y0 = plo0 * cl.x - phi0 * sl.x;
                        float y1 = plo1 * cl.y - phi1 * sl.y;
                        float y2 = phi0 * ch.x + plo0 * sh.x;
                        float y3 = phi1 * ch.y + plo1 * sh.y;
                        *reinterpret_cast<unsigned*>(op + jlo) = pk(y0, y1);
                        *reinterpret_cast<unsigned*>(op + jhi) = pk(y2, y3);
                    }
                }
            } else {
                // V: +bias -> transpose into sVt[(mh*32+j)*104 + t]
                #pragma unroll
                for (int r = 0; r < 2; r++) {
                    int t = c * 32 + mrow + gq + 8 * r;
                    #pragma unroll
                    for (int ntl = 0; ntl < 2; ntl++) {
                        int jlo = ntl * 8 + 2 * t4;
                        int jhi = jlo + 16;
                        float2 blo = *reinterpret_cast<const float2*>(&bia[mh * 32 + jlo]);
                        float2 bhi = *reinterpret_cast<const float2*>(&bia[mh * 32 + jhi]);
                        sVt[(mh * 32 + jlo) * 104 + t]     = __float2bfloat16(acc[ntl][2 * r] + blo.x);
                        sVt[(mh * 32 + jlo + 1) * 104 + t] = __float2bfloat16(acc[ntl][2 * r + 1] + blo.y);
                        sVt[(mh * 32 + jhi) * 104 + t]     = __float2bfloat16(acc[ntl + 2][2 * r] + bhi.x);
                        sVt[(mh * 32 + jhi + 1) * 104 + t] = __float2bfloat16(acc[ntl + 2][2 * r + 1] + bhi.y);
                    }
                }
            }
            __syncthreads();
        }
    }

    // ---- load wq -> sW0 ----
    {
        const unsigned* s0 = reinterpret_cast<const unsigned*>(g_wq);
        unsigned* d0 = reinterpret_cast<unsigned*>(sW0);
        for (int i = tid; i < 8192; i += 512) {
            d0[(i >> 6) * 68 + (i & 63)] = s0[i];
        }
    }
    __syncthreads();

    // =========================== Phase B: Q prep + attention + mean-accumulate ===========================
    __nv_bfloat16* sKh = sK + mh * 96 * 40;
    __nv_bfloat16* sVh = sVt + mh * 32 * 104;
    unsigned kb[6], vb[2];
    #pragma unroll
    for (int p = 0; p < 6; p++)
        kb[p] = ssa(&sKh[((2 * p + (lane >> 4)) * 8 + (lane & 7)) * 40 + (((lane >> 3) & 1) << 3)]);
    #pragma unroll
    for (int p = 0; p < 2; p++)
        vb[p] = ssa(&sVh[((2 * p + (lane >> 4)) * 8 + (lane & 7)) * 104 + (((lane >> 3) & 1) << 3)]);
    unsigned qb0 = ssa(&sW0[(mh * 32 + ((lane >> 4) * 8) + (lane & 7)) * 136 + (((lane >> 3) & 1) << 3)]);
    unsigned qb1 = qb0 + 16 * 136 * 2;
    float sc = g_scales[mh];

    float moacc[4][4] = {};   // mean-over-views accumulator (uv-rows x head-cols tile)

    for (int it = 0; it < 6; it++) {
        int c = 2 * it + g;   // chunk of 32 q-rows; view n == it
        // LayerNorm
        {
            int row = tl >> 3, sub = tl & 7;
            int t = c * 32 + row;
            int n = t >> 6, rem = t & 63;
            const float* src = q + ((size_t)(n * LTOT + l) * 64 + rem) * 128 + sub * 16;
            float vv[16];
            #pragma unroll
            for (int i = 0; i < 4; i++) {
                float4 f = reinterpret_cast<const float4*>(src)[i];
                vv[4 * i] = f.x; vv[4 * i + 1] = f.y; vv[4 * i + 2] = f.z; vv[4 * i + 3] = f.w;
            }
            float s = 0.f;
            #pragma unroll
            for (int i = 0; i < 16; i++) s += vv[i];
            #pragma unroll
            for (int o = 1; o < 8; o <<= 1) s += __shfl_xor_sync(0xffffffffu, s, o);
            float mu = s * (1.0f / 128.0f);
            float q2 = 0.f;
            #pragma unroll
            for (int i = 0; i < 16; i++) { float d = vv[i] - mu; q2 += d * d; }
            #pragma unroll
            for (int o = 1; o < 8; o <<= 1) q2 += __shfl_xor_sync(0xffffffffu, q2, o);
            float rs = rsqrtf(q2 * (1.0f / 128.0f) + 1e-5f);
            unsigned* xdst = reinterpret_cast<unsigned*>(sXg) + row * 68 + sub * 8;
            #pragma unroll
            for (int i = 0; i < 8; i++) {
                int c0 = sub * 16 + 2 * i;
                float a0 = (vv[2 * i] - mu) * rs * lnqg[c0] + lnqb[c0];
                float a1 = (vv[2 * i + 1] - mu) * rs * lnqg[c0 + 1] + lnqb[c0 + 1];
                xdst[i] = pk(a0, a1);
            }
        }
        __syncthreads();

        // q-projection GEMM (16 rows x 32 cols of head mh)
        float acc[4][4] = {};
        #pragma unroll
        for (int kk = 0; kk < 128; kk += 16) {
            unsigned a[4], b01[4], b23[4];
            ldsm4(a, abaseA + kk * 2);
            ldsm4(b01, qb0 + kk * 2);
            ldsm4(b23, qb1 + kk * 2);
            mma16816(acc[0], a, &b01[0]);
            mma16816(acc[1], a, &b01[2]);
            mma16816(acc[2], a, &b23[0]);
            mma16816(acc[3], a, &b23[2]);
        }

        // epilogue in registers: +bias -> RoPE -> *scale -> pack into A fragments
        unsigned aq0[4], aq1[4];
        {
            float F[4][4];
            #pragma unroll
            for (int r = 0; r < 2; r++) {
                int t = c * 32 + mrow + gq + 8 * r;
                #pragma unroll
                for (int ntl = 0; ntl < 2; ntl++) {
                    int jlo = ntl * 8 + 2 * t4;
                    int jhi = jlo + 16;
                    float2 blo = *reinterpret_cast<const float2*>(&bq[mh * 32 + jlo]);
                    float2 bhi = *reinterpret_cast<const float2*>(&bq[mh * 32 + jhi]);
                    float plo0 = acc[ntl][2 * r] + blo.x;
                    float plo1 = acc[ntl][2 * r + 1] + blo.y;
                    float phi0 = acc[ntl + 2][2 * r] + bhi.x;
                    float phi1 = acc[ntl + 2][2 * r + 1] + bhi.y;
                    float2 cl = *reinterpret_cast<const float2*>(&g_cos[t * 32 + jlo]);
                    float2 sl = *reinterpret_cast<const float2*>(&g_sin[t * 32 + jlo]);
                    float2 ch = *reinterpret_cast<const float2*>(&g_cos[t * 32 + jhi]);
                    float2 sh = *reinterpret_cast<const float2*>(&g_sin[t * 32 + jhi]);
                    F[ntl][2 * r]         = (plo0 * cl.x - phi0 * sl.x) * sc;
                    F[ntl][2 * r + 1]     = (plo1 * cl.y - phi1 * sl.y) * sc;
                    F[ntl + 2][2 * r]     = (phi0 * ch.x + plo0 * sh.x) * sc;
                    F[ntl + 2][2 * r + 1] = (phi1 * ch.y + plo1 * sh.y) * sc;
                }
            }
            aq0[0] = pk(F[0][0], F[0][1]); aq0[1] = pk(F[0][2], F[0][3]);
            aq0[2] = pk(F[1][0], F[1][1]); aq0[3] = pk(F[1][2], F[1][3]);
            aq1[0] = pk(F[2][0], F[2][1]); aq1[1] = pk(F[2][2], F[2][3]);
            aq1[2] = pk(F[3][0], F[3][1]); aq1[3] = pk(F[3][2], F[3][3]);
        }

        // S = Q K^T over 96 keys
        float sacc[12][4] = {};
        #pragma unroll
        for (int p = 0; p < 6; p++) {
            unsigned b[4];
            ldsm4(b, kb[p]);
            mma16816(sacc[2 * p], aq0, &b[0]);
            mma16816(sacc[2 * p + 1], aq0, &b[2]);
        }
        #pragma unroll
        for (int p = 0; p < 6; p++) {
            unsigned b[4];
            ldsm4(b, kb[p] + 32);
            mma16816(sacc[2 * p], aq1, &b[0]);
            mma16816(sacc[2 * p + 1], aq1, &b[2]);
        }

        // softmax over 96 (row spread across 4 quad lanes)
        float mx0 = -1e30f, mx1 = -1e30f;
        #pragma unroll
        for (int nt = 0; nt < 12; nt++) {
            mx0 = fmaxf(mx0, fmaxf(sacc[nt][0], sacc[nt][1]));
            mx1 = fmaxf(mx1, fmaxf(sacc[nt][2], sacc[nt][3]));
        }
        mx0 = fmaxf(mx0, __shfl_xor_sync(0xffffffffu, mx0, 1));
        mx0 = fmaxf(mx0, __shfl_xor_sync(0xffffffffu, mx0, 2));
        mx1 = fmaxf(mx1, __shfl_xor_sync(0xffffffffu, mx1, 1));
        mx1 = fmaxf(mx1, __shfl_xor_sync(0xffffffffu, mx1, 2));
        float sm0 = 0.f, sm1 = 0.f;
        #pragma unroll
        for (int nt = 0; nt < 12; nt++) {
            sacc[nt][0] = __expf(sacc[nt][0] - mx0);
            sacc[nt][1] = __expf(sacc[nt][1] - mx0);
            sacc[nt][2] = __expf(sacc[nt][2] - mx1);
            sacc[nt][3] = __expf(sacc[nt][3] - mx1);
            sm0 += sacc[nt][0] + sacc[nt][1];
            sm1 += sacc[nt][2] + sacc[nt][3];
        }
        sm0 += __shfl_xor_sync(0xffffffffu, sm0, 1);
        sm0 += __shfl_xor_sync(0xffffffffu, sm0, 2);
        sm1 += __shfl_xor_sync(0xffffffffu, sm1, 1);
        sm1 += __shfl_xor_sync(0xffffffffu, sm1, 2);
        float r0i = 1.0f / sm0, r1i = 1.0f / sm1;
        #pragma unroll
        for (int nt = 0; nt < 12; nt++) {
            sacc[nt][0] *= r0i; sacc[nt][1] *= r0i;
            sacc[nt][2] *= r1i; sacc[nt][3] *= r1i;
        }

        // O += P V : accumulate mean-over-views directly in moacc
        #pragma unroll
        for (int c6 = 0; c6 < 6; c6++) {
            unsigned a[4];
            a[0] = pk(sacc[2 * c6][0], sacc[2 * c6][1]);
            a[1] = pk(sacc[2 * c6][2], sacc[2 * c6][3]);
            a[2] = pk(sacc[2 * c6 + 1][0], sacc[2 * c6 + 1][1]);
            a[3] = pk(sacc[2 * c6 + 1][2], sacc[2 * c6 + 1][3]);
            #pragma unroll
            for (int p = 0; p < 2; p++) {
                unsigned b[4];
                ldsm4(b, vb[p] + c6 * 32);
                mma16816(moacc[2 * p], a, &b[0]);
                mma16816(moacc[2 * p + 1], a, &b[2]);
            }
        }
        __syncthreads();
    }

    // =========================== Phase C: mean -> proj -> +skip -> out ===========================
    // load wp -> sW0 (wq reads all completed at last sync)
    {
        const unsigned* s0 = reinterpret_cast<const unsigned*>(g_wp);
        unsigned* d0 = reinterpret_cast<unsigned*>(sW0);
        for (int i = tid; i < 8192; i += 512) {
            d0[(i >> 6) * 68 + (i & 63)] = s0[i];
        }
    }
    // write mean tile into sX (as sO: 64 rows x 136)
    {
        int uv0 = g * 32 + mrow;
        #pragma unroll
        for (int nt = 0; nt < 4; nt++) {
            int col = mh * 32 + nt * 8 + 2 * t4;
            #pragma unroll
            for (int r = 0; r < 2; r++) {
                int uvr = uv0 + gq + 8 * r;
                *reinterpret_cast<unsigned*>(&sX[uvr * 136 + col]) =
                    pk(moacc[nt][2 * r] * (1.0f / 6.0f), moacc[nt][2 * r + 1] * (1.0f / 6.0f));
            }
        }
    }
    __syncthreads();

    // proj GEMM: 64 rows x 128 cols; warp = (rowtile wid&3, coltile wid>>2)
    {
        int mrow2 = (wid & 3) * 16, cw = (wid >> 2) * 32;
        unsigned abase2 = ssa(&sX[(mrow2 + (lane & 15)) * 136 + ((lane >> 4) << 3)]);
        unsigned pb0 = ssa(&sW0[(cw + ((lane >> 4) * 8) + (lane & 7)) * 136 + (((lane >> 3) & 1) << 3)]);
        unsigned pb1 = pb0 + 16 * 136 * 2;
        float pacc[4][4] = {};
        #pragma unroll
        for (int kk = 0; kk < 128; kk += 16) {
            unsigned a[4], b01[4], b23[4];
            ldsm4(a, abase2 + kk * 2);
            ldsm4(b01, pb0 + kk * 2);
            ldsm4(b23, pb1 + kk * 2);
            mma16816(pacc[0], a, &b01[0]);
            mma16816(pacc[1], a, &b01[2]);
            mma16816(pacc[2], a, &b23[0]);
            mma16816(pacc[3], a, &b23[2]);
        }
        #pragma unroll
        for (int nt = 0; nt < 4; nt++) {
            int col = cw + nt * 8 + 2 * t4;
            float2 bp = *reinterpret_cast<const float2*>(&bproj[col]);
            #pragma unroll
            for (int r = 0; r < 2; r++) {
                int rowg = l * 64 + mrow2 + gq + 8 * r;
                float2 sk = *reinterpret_cast<const float2*>(skip + (size_t)rowg * 128 + col);
                float2 o2;
                o2.x = pacc[nt][2 * r] + bp.x + sk.x;
                o2.y = pacc[nt][2 * r + 1] + bp.y + sk.y;
                *reinterpret_cast<float2*>(out + (size_t)rowg * 128 + col) = o2;
            }
        }
    }
}

// ---------------- launch ----------------
extern "C" void kernel_launch(void* const* d_in, const int* in_sizes, int n_in,
                              void* d_out, int out_size) {
    const float* q     = (const float*)d_in[0];
    const float* k     = (const float*)d_in[1];
    const float* v     = (const float*)d_in[2];
    const float* skip  = (const float*)d_in[3];
    const float* freqs = (const float*)d_in[4];
    const float* gate  = (const float*)d_in[5];
    const float* lnqg  = (const float*)d_in[6];
    const float* lnqb  = (const float*)d_in[7];
    const float* lnkg  = (const float*)d_in[8];
    const float* lnkb  = (const float*)d_in[9];
    const float* lnvg  = (const float*)d_in[10];
    const float* lnvb  = (const float*)d_in[11];
    const float* wq    = (const float*)d_in[12];
    const float* bq    = (const float*)d_in[13];
    const float* wk    = (const float*)d_in[14];
    const float* bk    = (const float*)d_in[15];
    const float* wv    = (const float*)d_in[16];
    const float* bv    = (const float*)d_in[17];
    const float* wproj = (const float*)d_in[18];
    const float* bproj = (const float*)d_in[19];
    const float* als   = (const float*)d_in[20];
    float* out = (float*)d_out;

    static int smem_set = 0;
    if (!smem_set) {
        cudaFuncSetAttribute(fused_kernel, cudaFuncAttributeMaxDynamicSharedMemorySize, SMEM_BYTES);
        smem_set = 1;
    }

    prep_const_kernel<<<305, 256>>>(wq, wk, wv, wproj, freqs, gate, als);
    fused_kernel<<<LTOT, 512, SMEM_BYTES>>>(q, k, v, skip,
                                            lnqg, lnqb, lnkg, lnkb, lnvg, lnvb,
                                            bq, bk, bv, bproj, out);
}

// round 5
// speedup vs baseline: 1.6115x; 1.3700x over previous
#include <cuda_runtime.h>
#include <cuda_bf16.h>
#include <math.h>

// ---------------- problem constants ----------------
// B=1, N=6, X=Y=25 (L=625), W1=W2=8 (Qn=384), w1=w2=4 (Kn=96), D=128, M=4 heads, dh=32

#define LTOT 625
#define QN   384
#define KN   96

// ---------------- device constants (converted once) ----------------
__device__ __nv_bfloat16 g_wq[16384];
__device__ __nv_bfloat16 g_wkw[16384];
__device__ __nv_bfloat16 g_wv[16384];
__device__ __nv_bfloat16 g_wp[16384];
__device__ float g_cos[QN * 32];
__device__ float g_sin[QN * 32];
__device__ float g_scales[4];

// ---------------- helpers ----------------
__device__ __forceinline__ unsigned pk(float a, float b) {
    __nv_bfloat162 h = __floats2bfloat162_rn(a, b);
    return *reinterpret_cast<unsigned*>(&h);
}
__device__ __forceinline__ unsigned ssa(const void* p) {
    return (unsigned)__cvta_generic_to_shared(p);
}
__device__ __forceinline__ void ldsm4(unsigned r[4], unsigned addr) {
    asm volatile("ldmatrix.sync.aligned.m8n8.x4.shared.b16 {%0,%1,%2,%3}, [%4];\n"
                 : "=r"(r[0]), "=r"(r[1]), "=r"(r[2]), "=r"(r[3]) : "r"(addr));
}
__device__ __forceinline__ void mma16816(float c[4], const unsigned a[4], const unsigned b[2]) {
    asm volatile(
        "mma.sync.aligned.m16n8k16.row.col.f32.bf16.bf16.f32 "
        "{%0,%1,%2,%3}, {%4,%5,%6,%7}, {%8,%9}, {%0,%1,%2,%3};\n"
        : "+f"(c[0]), "+f"(c[1]), "+f"(c[2]), "+f"(c[3])
        : "r"(a[0]), "r"(a[1]), "r"(a[2]), "r"(a[3]), "r"(b[0]), "r"(b[1]));
}
__device__ __forceinline__ void cpa16(void* dst, const void* src) {
    asm volatile("cp.async.cg.shared.global [%0], [%1], 16;\n"
                 :: "r"(ssa(dst)), "l"(src));
}
__device__ __forceinline__ void cpa_commit() {
    asm volatile("cp.async.commit_group;\n");
}
template<int N> __device__ __forceinline__ void cpa_wait() {
    asm volatile("cp.async.wait_group %0;\n" :: "n"(N));
}
__device__ __forceinline__ void barg(int id) {
    asm volatile("bar.sync %0, %1;\n" :: "r"(id), "r"(256) : "memory");
}

// ---------------- kernel 0: constants prep ----------------
__global__ __launch_bounds__(256) void prep_const_kernel(
    const float* __restrict__ wq, const float* __restrict__ wk,
    const float* __restrict__ wv, const float* __restrict__ wp,
    const float* __restrict__ freqs, const float* __restrict__ gate,
    const float* __restrict__ als)
{
    int idx = blockIdx.x * 256 + threadIdx.x;
    if (idx < 16384) {
        g_wq[idx] = __float2bfloat16(wq[idx]);
    } else if (idx < 32768) {
        g_wkw[idx - 16384] = __float2bfloat16(wk[idx - 16384]);
    } else if (idx < 49152) {
        g_wv[idx - 32768] = __float2bfloat16(wv[idx - 32768]);
    } else if (idx < 65536) {
        g_wp[idx - 49152] = __float2bfloat16(wp[idx - 49152]);
    } else if (idx < 65536 + QN * 32) {
        int j = idx - 65536;
        float f = freqs[j];            // (400,32) row-major, t<384 prefix
        g_cos[j] = cosf(f);
        g_sin[j] = sinf(f);
    } else if (idx < 65536 + QN * 32 + 4) {
        int m = idx - (65536 + QN * 32);
        float temp = als[m] - 0.5f * logf(32.0f);   // als + log(dh^-0.5)
        float ga = fminf(fmaxf(gate[m], 0.0f), 1.0f);
        g_scales[m] = temp * ga;
    }
}

// ---------------- fused kernel: one block per l-tile ----------------
// smem element offsets (bf16 elems):
//   sK   : 4 heads * 96 * 40            = 15360
//   sVt  : 4 heads * 32 * 104           = 13312
//   sW0  : 128 * 136                    = 17408
//   sW1  : 128 * 136                    = 17408
//   sX   : 64 * 136                     =  8704
//   sRaw : 2 groups * 2 bufs * 4096 f32 = 32768 f32 = 65536 elems
#define E_K   0
#define E_VT  15360
#define E_W0  28672
#define E_W1  46080
#define E_X   63488
#define E_RAW 72192
#define SMEM_ELEMS (72192 + 32768)
#define SMEM_BYTES (SMEM_ELEMS * 2)

__global__ __launch_bounds__(512, 1) void fused_kernel(
    const float* __restrict__ q, const float* __restrict__ k,
    const float* __restrict__ v, const float* __restrict__ skip,
    const float* __restrict__ lnqg, const float* __restrict__ lnqb,
    const float* __restrict__ lnkg, const float* __restrict__ lnkb,
    const float* __restrict__ lnvg, const float* __restrict__ lnvb,
    const float* __restrict__ bq, const float* __restrict__ bk,
    const float* __restrict__ bv, const float* __restrict__ bproj,
    float* __restrict__ out)
{
    extern __shared__ __nv_bfloat16 sm[];
    __nv_bfloat16* sK  = sm + E_K;
    __nv_bfloat16* sVt = sm + E_VT;
    __nv_bfloat16* sW0 = sm + E_W0;
    __nv_bfloat16* sW1 = sm + E_W1;
    __nv_bfloat16* sX  = sm + E_X;
    float* sRawAll = reinterpret_cast<float*>(sm + E_RAW);

    int l = blockIdx.x;
    int tid = threadIdx.x;
    int g = tid >> 8;              // thread group (0/1), 256 threads each
    int tl = tid & 255;
    int wid = tid >> 5, lane = tid & 31;
    int wg = wid & 7;              // warp index within group
    int gq = lane >> 2, t4 = lane & 3;
    int bid = 1 + g;               // named barrier id for this group

    int mrow = (wg & 1) * 16;      // row-half within 32-row chunk
    int mh = wg >> 1;              // head

    float* rb[2] = { sRawAll + g * 8192, sRawAll + g * 8192 + 4096 };

    __nv_bfloat16* sXg = sX + g * 32 * 136;
    unsigned abaseA = ssa(&sXg[(mrow + (lane & 15)) * 136 + ((lane >> 4) << 3)]);

    int lrow = tl >> 3, lsub = tl & 7;   // LN mapping: 8 threads/row

    // =========================== Phase A: K (group 0) / V (group 1) ===========================
    const float* xin  = g ? v : k;
    {
        // cp.async: own-group weight matrix
        const __nv_bfloat16* wsrc = g ? g_wv : g_wkw;
        __nv_bfloat16* wdst = g ? sW1 : sW0;
        #pragma unroll
        for (int i = tl; i < 2048; i += 256)
            cpa16(wdst + (i >> 4) * 136 + (i & 15) * 8, wsrc + i * 8);
        cpa_commit();
        // prefetch kv chunks 0, 1
        #pragma unroll
        for (int c = 0; c < 2; c++) {
            float* dst = rb[c];
            #pragma unroll
            for (int j = 0; j < 4; j++) {
                int i = tl + 256 * j;
                int row = i >> 5, col = i & 31;
                int t = c * 32 + row;
                int n = t >> 4, rem = t & 15;
                cpa16(dst + row * 128 + col * 4,
                      xin + ((size_t)(n * LTOT + l) * 16 + rem) * 128 + col * 4);
            }
            cpa_commit();
        }
    }

    {
        const float* lng  = g ? lnvg : lnkg;
        const float* lnb_ = g ? lnvb : lnkb;
        const float* bia  = g ? bv : bk;
        __nv_bfloat16* sWg = g ? sW1 : sW0;
        unsigned bbase0 = ssa(&sWg[(mh * 32 + ((lane >> 4) * 8) + (lane & 7)) * 136 + (((lane >> 3) & 1) << 3)]);
        unsigned bbase1 = bbase0 + 16 * 136 * 2;

        for (int c = 0; c < 3; c++) {
            if (c < 2) cpa_wait<1>(); else cpa_wait<0>();
            barg(bid);

            // LayerNorm 32 rows from smem raw (conflict-free stride-32 mapping)
            float vv[16];
            {
                const float* rp = rb[c & 1] + lrow * 128;
                #pragma unroll
                for (int i = 0; i < 4; i++) {
                    float4 f = *reinterpret_cast<const float4*>(rp + (lsub + 8 * i) * 4);
                    vv[4 * i] = f.x; vv[4 * i + 1] = f.y; vv[4 * i + 2] = f.z; vv[4 * i + 3] = f.w;
                }
                float s = 0.f;
                #pragma unroll
                for (int i = 0; i < 16; i++) s += vv[i];
                #pragma unroll
                for (int o = 1; o < 8; o <<= 1) s += __shfl_xor_sync(0xffffffffu, s, o);
                float mu = s * (1.0f / 128.0f);
                float q2 = 0.f;
                #pragma unroll
                for (int i = 0; i < 16; i++) { float d = vv[i] - mu; q2 += d * d; }
                #pragma unroll
                for (int o = 1; o < 8; o <<= 1) q2 += __shfl_xor_sync(0xffffffffu, q2, o);
                float rs = rsqrtf(q2 * (1.0f / 128.0f) + 1e-5f);
                unsigned* xw = reinterpret_cast<unsigned*>(sXg) + lrow * 68;
                #pragma unroll
                for (int i = 0; i < 4; i++) {
                    int c0 = lsub * 4 + i * 32;
                    float a0 = (vv[4 * i]     - mu) * rs * lng[c0]     + lnb_[c0];
                    float a1 = (vv[4 * i + 1] - mu) * rs * lng[c0 + 1] + lnb_[c0 + 1];
                    float a2 = (vv[4 * i + 2] - mu) * rs * lng[c0 + 2] + lnb_[c0 + 2];
                    float a3 = (vv[4 * i + 3] - mu) * rs * lng[c0 + 3] + lnb_[c0 + 3];
                    xw[2 * lsub + 16 * i]     = pk(a0, a1);
                    xw[2 * lsub + 16 * i + 1] = pk(a2, a3);
                }
            }
            barg(bid);

            // prefetch chunk c+2 into the buffer LN just released
            if (c == 0) {
                float* dst = rb[0];
                #pragma unroll
                for (int j = 0; j < 4; j++) {
                    int i = tl + 256 * j;
                    int row = i >> 5, col = i & 31;
                    int t = 2 * 32 + row;
                    int n = t >> 4, rem = t & 15;
                    cpa16(dst + row * 128 + col * 4,
                          xin + ((size_t)(n * LTOT + l) * 16 + rem) * 128 + col * 4);
                }
                cpa_commit();
            }

            float acc[4][4] = {};
            #pragma unroll
            for (int kk = 0; kk < 128; kk += 16) {
                unsigned a[4], b01[4], b23[4];
                ldsm4(a, abaseA + kk * 2);
                ldsm4(b01, bbase0 + kk * 2);
                ldsm4(b23, bbase1 + kk * 2);
                mma16816(acc[0], a, &b01[0]);
                mma16816(acc[1], a, &b01[2]);
                mma16816(acc[2], a, &b23[0]);
                mma16816(acc[3], a, &b23[2]);
            }

            if (g == 0) {
                // K: +bias -> RoPE -> sK[(mh*96+t)*40 + j]
                #pragma unroll
                for (int r = 0; r < 2; r++) {
                    int t = c * 32 + mrow + gq + 8 * r;
                    __nv_bfloat16* op = sK + (mh * 96 + t) * 40;
                    #pragma unroll
                    for (int ntl = 0; ntl < 2; ntl++) {
                        int jlo = ntl * 8 + 2 * t4;
                        int jhi = jlo + 16;
                        float2 blo = *reinterpret_cast<const float2*>(&bia[mh * 32 + jlo]);
                        float2 bhi = *reinterpret_cast<const float2*>(&bia[mh * 32 + jhi]);
                        float plo0 = acc[ntl][2 * r] + blo.x;
                        float plo1 = acc[ntl][2 * r + 1] + blo.y;
                        float phi0 = acc[ntl + 2][2 * r] + bhi.x;
                        float phi1 = acc[ntl + 2][2 * r + 1] + bhi.y;
                        float2 cl = *reinterpret_cast<const float2*>(&g_cos[t * 32 + jlo]);
                        float2 sl = *reinterpret_cast<const float2*>(&g_sin[t * 32 + jlo]);
                        float2 ch = *reinterpret_cast<const float2*>(&g_cos[t * 32 + jhi]);
                        float2 sh = *reinterpret_cast<const float2*>(&g_sin[t * 32 + jhi]);
                        float y0 = plo0 * cl.x - phi0 * sl.x;
                        float y1 = plo1 * cl.y - phi1 * sl.y;
                        float y2 = phi0 * ch.x + plo0 * sh.x;
                        float y3 = phi1 * ch.y + plo1 * sh.y;
                        *reinterpret_cast<unsigned*>(op + jlo) = pk(y0, y1);
                        *reinterpret_cast<unsigned*>(op + jhi) = pk(y2, y3);
                    }
                }
            } else {
                // V: +bias -> transpose into sVt[(mh*32+j)*104 + t]
                #pragma unroll
                for (int r = 0; r < 2; r++) {
                    int t = c * 32 + mrow + gq + 8 * r;
                    #pragma unroll
                    for (int ntl = 0; ntl < 2; ntl++) {
                        int jlo = ntl * 8 + 2 * t4;
                        int jhi = jlo + 16;
                        float2 blo = *reinterpret_cast<const float2*>(&bv[mh * 32 + jlo]);
                        float2 bhi = *reinterpret_cast<const float2*>(&bv[mh * 32 + jhi]);
                        sVt[(mh * 32 + jlo) * 104 + t]     = __float2bfloat16(acc[ntl][2 * r] + blo.x);
                        sVt[(mh * 32 + jlo + 1) * 104 + t] = __float2bfloat16(acc[ntl][2 * r + 1] + blo.y);
                        sVt[(mh * 32 + jhi) * 104 + t]     = __float2bfloat16(acc[ntl + 2][2 * r] + bhi.x);
                        sVt[(mh * 32 + jhi + 1) * 104 + t] = __float2bfloat16(acc[ntl + 2][2 * r + 1] + bhi.y);
                    }
                }
            }
            barg(bid);
        }
    }

    __syncthreads();   // sK/sVt complete; sW0 free for wq

    // ---- cp.async: wq -> sW0 (block-wide), prefetch q chunks for iters 0,1 ----
    {
        #pragma unroll
        for (int i = tid; i < 2048; i += 512)
            cpa16(sW0 + (i >> 4) * 136 + (i & 15) * 8, g_wq + i * 8);
        cpa_commit();
        #pragma unroll
        for (int it = 0; it < 2; it++) {
            int c = 2 * it + g;
            float* dst = rb[it & 1];
            #pragma unroll
            for (int j = 0; j < 4; j++) {
                int i = tl + 256 * j;
                int row = i >> 5, col = i & 31;
                int t = c * 32 + row;
                int n = t >> 6, rem = t & 63;
                cpa16(dst + row * 128 + col * 4,
                      q + ((size_t)(n * LTOT + l) * 64 + rem) * 128 + col * 4);
            }
            cpa_commit();
        }
    }

    // =========================== Phase B: Q prep + attention + mean-accumulate ===========================
    __nv_bfloat16* sKh = sK + mh * 96 * 40;
    __nv_bfloat16* sVh = sVt + mh * 32 * 104;
    unsigned kb[6], vb[2];
    #pragma unroll
    for (int p = 0; p < 6; p++)
        kb[p] = ssa(&sKh[((2 * p + (lane >> 4)) * 8 + (lane & 7)) * 40 + (((lane >> 3) & 1) << 3)]);
    #pragma unroll
    for (int p = 0; p < 2; p++)
        vb[p] = ssa(&sVh[((2 * p + (lane >> 4)) * 8 + (lane & 7)) * 104 + (((lane >> 3) & 1) << 3)]);
    unsigned qb0 = ssa(&sW0[(mh * 32 + ((lane >> 4) * 8) + (lane & 7)) * 136 + (((lane >> 3) & 1) << 3)]);
    unsigned qb1 = qb0 + 16 * 136 * 2;
    float sc = g_scales[mh];

    float moacc[4][4] = {};   // mean-over-views accumulator

    for (int it = 0; it < 6; it++) {
        int c = 2 * it + g;
        if (it < 5) cpa_wait<1>(); else cpa_wait<0>();
        if (it == 0) __syncthreads(); else barg(bid);

        // LayerNorm from smem raw
        float vv[16];
        {
            const float* rp = rb[it & 1] + lrow * 128;
            #pragma unroll
            for (int i = 0; i < 4; i++) {
                float4 f = *reinterpret_cast<const float4*>(rp + (lsub + 8 * i) * 4);
                vv[4 * i] = f.x; vv[4 * i + 1] = f.y; vv[4 * i + 2] = f.z; vv[4 * i + 3] = f.w;
            }
            float s = 0.f;
            #pragma unroll
            for (int i = 0; i < 16; i++) s += vv[i];
            #pragma unroll
            for (int o = 1; o < 8; o <<= 1) s += __shfl_xor_sync(0xffffffffu, s, o);
            float mu = s * (1.0f / 128.0f);
            float q2 = 0.f;
            #pragma unroll
            for (int i = 0; i < 16; i++) { float d = vv[i] - mu; q2 += d * d; }
            #pragma unroll
            for (int o = 1; o < 8; o <<= 1) q2 += __shfl_xor_sync(0xffffffffu, q2, o);
            float rs = rsqrtf(q2 * (1.0f / 128.0f) + 1e-5f);
            unsigned* xw = reinterpret_cast<unsigned*>(sXg) + lrow * 68;
            #pragma unroll
            for (int i = 0; i < 4; i++) {
                int c0 = lsub * 4 + i * 32;
                float a0 = (vv[4 * i]     - mu) * rs * lnqg[c0]     + lnqb[c0];
                float a1 = (vv[4 * i + 1] - mu) * rs * lnqg[c0 + 1] + lnqb[c0 + 1];
                float a2 = (vv[4 * i + 2] - mu) * rs * lnqg[c0 + 2] + lnqb[c0 + 2];
                float a3 = (vv[4 * i + 3] - mu) * rs * lnqg[c0 + 3] + lnqb[c0 + 3];
                xw[2 * lsub + 16 * i]     = pk(a0, a1);
                xw[2 * lsub + 16 * i + 1] = pk(a2, a3);
            }
        }
        barg(bid);

        // prefetch q chunk for iter it+2 into released buffer
        if (it < 4) {
            int c2 = 2 * (it + 2) + g;
            float* dst = rb[it & 1];
            #pragma unroll
            for (int j = 0; j < 4; j++) {
                int i = tl + 256 * j;
                int row = i >> 5, col = i & 31;
                int t = c2 * 32 + row;
                int n = t >> 6, rem = t & 63;
                cpa16(dst + row * 128 + col * 4,
                      q + ((size_t)(n * LTOT + l) * 64 + rem) * 128 + col * 4);
            }
            cpa_commit();
        }

        // q-projection GEMM (16 rows x 32 cols of head mh)
        float acc[4][4] = {};
        #pragma unroll
        for (int kk = 0; kk < 128; kk += 16) {
            unsigned a[4], b01[4], b23[4];
            ldsm4(a, abaseA + kk * 2);
            ldsm4(b01, qb0 + kk * 2);
            ldsm4(b23, qb1 + kk * 2);
            mma16816(acc[0], a, &b01[0]);
            mma16816(acc[1], a, &b01[2]);
            mma16816(acc[2], a, &b23[0]);
            mma16816(acc[3], a, &b23[2]);
        }

        // epilogue in registers: +bias -> RoPE -> *scale -> A fragments
        unsigned aq0[4], aq1[4];
        {
            float F[4][4];
            #pragma unroll
            for (int r = 0; r < 2; r++) {
                int t = c * 32 + mrow + gq + 8 * r;
                #pragma unroll
                for (int ntl = 0; ntl < 2; ntl++) {
                    int jlo = ntl * 8 + 2 * t4;
                    int jhi = jlo + 16;
                    float2 blo = *reinterpret_cast<const float2*>(&bq[mh * 32 + jlo]);
                    float2 bhi = *reinterpret_cast<const float2*>(&bq[mh * 32 + jhi]);
                    float plo0 = acc[ntl][2 * r] + blo.x;
                    float plo1 = acc[ntl][2 * r + 1] + blo.y;
                    float phi0 = acc[ntl + 2][2 * r] + bhi.x;
                    float phi1 = acc[ntl + 2][2 * r + 1] + bhi.y;
                    float2 cl = *reinterpret_cast<const float2*>(&g_cos[t * 32 + jlo]);
                    float2 sl = *reinterpret_cast<const float2*>(&g_sin[t * 32 + jlo]);
                    float2 ch = *reinterpret_cast<const float2*>(&g_cos[t * 32 + jhi]);
                    float2 sh = *reinterpret_cast<const float2*>(&g_sin[t * 32 + jhi]);
                    F[ntl][2 * r]         = (plo0 * cl.x - phi0 * sl.x) * sc;
                    F[ntl][2 * r + 1]     = (plo1 * cl.y - phi1 * sl.y) * sc;
                    F[ntl + 2][2 * r]     = (phi0 * ch.x + plo0 * sh.x) * sc;
                    F[ntl + 2][2 * r + 1] = (phi1 * ch.y + plo1 * sh.y) * sc;
                }
            }
            aq0[0] = pk(F[0][0], F[0][1]); aq0[1] = pk(F[0][2], F[0][3]);
            aq0[2] = pk(F[1][0], F[1][1]); aq0[3] = pk(F[1][2], F[1][3]);
            aq1[0] = pk(F[2][0], F[2][1]); aq1[1] = pk(F[2][2], F[2][3]);
            aq1[2] = pk(F[3][0], F[3][1]); aq1[3] = pk(F[3][2], F[3][3]);
        }

        // S = Q K^T over 96 keys
        float sacc[12][4] = {};
        #pragma unroll
        for (int p = 0; p < 6; p++) {
            unsigned b[4];
            ldsm4(b, kb[p]);
            mma16816(sacc[2 * p], aq0, &b[0]);
            mma16816(sacc[2 * p + 1], aq0, &b[2]);
        }
        #pragma unroll
        for (int p = 0; p < 6; p++) {
            unsigned b[4];
            ldsm4(b, kb[p] + 32);
            mma16816(sacc[2 * p], aq1, &b[0]);
            mma16816(sacc[2 * p + 1], aq1, &b[2]);
        }

        // softmax over 96
        float mx0 = -1e30f, mx1 = -1e30f;
        #pragma unroll
        for (int nt = 0; nt < 12; nt++) {
            mx0 = fmaxf(mx0, fmaxf(sacc[nt][0], sacc[nt][1]));
            mx1 = fmaxf(mx1, fmaxf(sacc[nt][2], sacc[nt][3]));
        }
        mx0 = fmaxf(mx0, __shfl_xor_sync(0xffffffffu, mx0, 1));
        mx0 = fmaxf(mx0, __shfl_xor_sync(0xffffffffu, mx0, 2));
        mx1 = fmaxf(mx1, __shfl_xor_sync(0xffffffffu, mx1, 1));
        mx1 = fmaxf(mx1, __shfl_xor_sync(0xffffffffu, mx1, 2));
        float sm0 = 0.f, sm1 = 0.f;
        #pragma unroll
        for (int nt = 0; nt < 12; nt++) {
            sacc[nt][0] = __expf(sacc[nt][0] - mx0);
            sacc[nt][1] = __expf(sacc[nt][1] - mx0);
            sacc[nt][2] = __expf(sacc[nt][2] - mx1);
            sacc[nt][3] = __expf(sacc[nt][3] - mx1);
            sm0 += sacc[nt][0] + sacc[nt][1];
            sm1 += sacc[nt][2] + sacc[nt][3];
        }
        sm0 += __shfl_xor_sync(0xffffffffu, sm0, 1);
        sm0 += __shfl_xor_sync(0xffffffffu, sm0, 2);
        sm1 += __shfl_xor_sync(0xffffffffu, sm1, 1);
        sm1 += __shfl_xor_sync(0xffffffffu, sm1, 2);
        float r0i = 1.0f / sm0, r1i = 1.0f / sm1;
        #pragma unroll
        for (int nt = 0; nt < 12; nt++) {
            sacc[nt][0] *= r0i; sacc[nt][1] *= r0i;
            sacc[nt][2] *= r1i; sacc[nt][3] *= r1i;
        }

        // O += P V
        #pragma unroll
        for (int c6 = 0; c6 < 6; c6++) {
            unsigned a[4];
            a[0] = pk(sacc[2 * c6][0], sacc[2 * c6][1]);
            a[1] = pk(sacc[2 * c6][2], sacc[2 * c6][3]);
            a[2] = pk(sacc[2 * c6 + 1][0], sacc[2 * c6 + 1][1]);
            a[3] = pk(sacc[2 * c6 + 1][2], sacc[2 * c6 + 1][3]);
            #pragma unroll
            for (int p = 0; p < 2; p++) {
                unsigned b[4];
                ldsm4(b, vb[p] + c6 * 32);
                mma16816(moacc[2 * p], a, &b[0]);
                mma16816(moacc[2 * p + 1], a, &b[2]);
            }
        }
        barg(bid);
    }

    // =========================== Phase C: mean -> proj -> +skip -> out ===========================
    __syncthreads();   // all reads of sW0 (wq) and sRaw done

    float* sSkipF = sRawAll;   // 64*128 floats
    {
        #pragma unroll
        for (int i = tid; i < 2048; i += 512)
            cpa16(sSkipF + i * 4, skip + (size_t)l * 8192 + i * 4);
        cpa_commit();
        #pragma unroll
        for (int i = tid; i < 2048; i += 512)
            cpa16(sW0 + (i >> 4) * 136 + (i & 15) * 8, g_wp + i * 8);
        cpa_commit();
    }
    // write mean tile into sX (64 rows x 136) while copies fly
    {
        int uv0 = g * 32 + mrow;
        #pragma unroll
        for (int nt = 0; nt < 4; nt++) {
            int col = mh * 32 + nt * 8 + 2 * t4;
            #pragma unroll
            for (int r = 0; r < 2; r++) {
                int uvr = uv0 + gq + 8 * r;
                *reinterpret_cast<unsigned*>(&sX[uvr * 136 + col]) =
                    pk(moacc[nt][2 * r] * (1.0f / 6.0f), moacc[nt][2 * r + 1] * (1.0f / 6.0f));
            }
        }
    }
    cpa_wait<0>();
    __syncthreads();

    // proj GEMM: 64 rows x 128 cols; warp = (rowtile wid&3, coltile wid>>2)
    {
        int mrow2 = (wid & 3) * 16, cw = (wid >> 2) * 32;
        unsigned abase2 = ssa(&sX[(mrow2 + (lane & 15)) * 136 + ((lane >> 4) << 3)]);
        unsigned pb0 = ssa(&sW0[(cw + ((lane >> 4) * 8) + (lane & 7)) * 136 + (((lane >> 3) & 1) << 3)]);
        unsigned pb1 = pb0 + 16 * 136 * 2;
        float pacc[4][4] = {};
        #pragma unroll
        for (int kk = 0; kk < 128; kk += 16) {
            unsigned a[4], b01[4], b23[4];
            ldsm4(a, abase2 + kk * 2);
            ldsm4(b01, pb0 + kk * 2);
            ldsm4(b23, pb1 + kk * 2);
            mma16816(pacc[0], a, &b01[0]);
            mma16816(pacc[1], a, &b01[2]);
            mma16816(pacc[2], a, &b23[0]);
            mma16816(pacc[3], a, &b23[2]);
        }
        #pragma unroll
        for (int nt = 0; nt < 4; nt++) {
            int col = cw + nt * 8 + 2 * t4;
            float2 bp = *reinterpret_cast<const float2*>(&bproj[col]);
            #pragma unroll
            for (int r = 0; r < 2; r++) {
                int rloc = mrow2 + gq + 8 * r;
                int rowg = l * 64 + rloc;
                float2 sk = *reinterpret_cast<const float2*>(sSkipF + rloc * 128 + col);
                float2 o2;
                o2.x = pacc[nt][2 * r] + bp.x + sk.x;
                o2.y = pacc[nt][2 * r + 1] + bp.y + sk.y;
                *reinterpret_cast<float2*>(out + (size_t)rowg * 128 + col) = o2;
            }
        }
    }
}

// ---------------- launch ----------------
extern "C" void kernel_launch(void* const* d_in, const int* in_sizes, int n_in,
                              void* d_out, int out_size) {
    const float* q     = (const float*)d_in[0];
    const float* k     = (const float*)d_in[1];
    const float* v     = (const float*)d_in[2];
    const float* skip  = (const float*)d_in[3];
    const float* freqs = (const float*)d_in[4];
    const float* gate  = (const float*)d_in[5];
    const float* lnqg  = (const float*)d_in[6];
    const float* lnqb  = (const float*)d_in[7];
    const float* lnkg  = (const float*)d_in[8];
    const float* lnkb  = (const float*)d_in[9];
    const float* lnvg  = (const float*)d_in[10];
    const float* lnvb  = (const float*)d_in[11];
    const float* wq    = (const float*)d_in[12];
    const float* bq    = (const float*)d_in[13];
    const float* wk    = (const float*)d_in[14];
    const float* bk    = (const float*)d_in[15];
    const float* wv    = (const float*)d_in[16];
    const float* bv    = (const float*)d_in[17];
    const float* wproj = (const float*)d_in[18];
    const float* bproj = (const float*)d_in[19];
    const float* als   = (const float*)d_in[20];
    float* out = (float*)d_out;

    static int smem_set = 0;
    if (!smem_set) {
        cudaFuncSetAttribute(fused_kernel, cudaFuncAttributeMaxDynamicSharedMemorySize, SMEM_BYTES);
        smem_set = 1;
    }

    prep_const_kernel<<<305, 256>>>(wq, wk, wv, wproj, freqs, gate, als);
    fused_kernel<<<LTOT, 512, SMEM_BYTES>>>(q, k, v, skip,
                                            lnqg, lnqb, lnkg, lnkb, lnvg, lnvb,
                                            bq, bk, bv, bproj, out);
}